// round 1
// baseline (speedup 1.0000x reference)
#include <cuda_runtime.h>

// PIANO_EnergyV: anisotropic diffusion (full symmetric D tensor) + upwind advection
// on a (2,160,160,160) fp32 grid, spacing h=1.
//
// Inputs (metadata order): C, Vx, Vy, Vz, Dxx, Dxy, Dxz, Dyy, Dyz, Dzz
// Output: same shape, fp32.
//
// Derivative semantics (match the JAX reference exactly):
//   fwd(i)  = X[min(i,n-2)+1] - X[min(i,n-2)]          (last voxel copies previous diff)
//   bwd(i)  = X[max(i,1)]     - X[max(i,1)-1]          (first voxel copies next diff)
//   cen(i)  = one-sided single diff at i=0 / i=n-1, else (X[i+1]-X[i-1])/2
//   bwd(fwd)(i) = 0 at i=n-1; C[2]-2C[1]+C[0] at i=0; else C[i+1]-2C[i]+C[i-1]
//   mixed dAb(dBf)(a,b) with a'=max(a,1), b'=min(b,n-2):
//       (X[a',b'+1]-X[a',b']) - (X[a'-1,b'+1]-X[a'-1,b'])

#define NN 160
#define SXX (NN*NN)
#define SYY (NN)

__global__ __launch_bounds__(NN)
void piano_energy_kernel(
    const float* __restrict__ C,
    const float* __restrict__ Vx,
    const float* __restrict__ Vy,
    const float* __restrict__ Vz,
    const float* __restrict__ Dxx,
    const float* __restrict__ Dxy,
    const float* __restrict__ Dxz,
    const float* __restrict__ Dyy,
    const float* __restrict__ Dyz,
    const float* __restrict__ Dzz,
    float* __restrict__ out)
{
    const int z = threadIdx.x;
    const int y = blockIdx.x;
    const int x = blockIdx.y;
    const int b = blockIdx.z;

    const int i = ((b * NN + x) * NN + y) * NN + z;

    // ---- per-axis clamped offsets ----
    // central: value = (F[i+d?p] - F[i+d?m]) * w?
    const int dxm = (x > 0)      ? -SXX : 0;
    const int dxp = (x < NN - 1) ?  SXX : 0;
    const float wx = (x > 0 && x < NN - 1) ? 0.5f : 1.0f;
    const int dym = (y > 0)      ? -SYY : 0;
    const int dyp = (y < NN - 1) ?  SYY : 0;
    const float wy = (y > 0 && y < NN - 1) ? 0.5f : 1.0f;
    const int dzm = (z > 0)      ? -1 : 0;
    const int dzp = (z < NN - 1) ?  1 : 0;
    const float wz = (z > 0 && z < NN - 1) ? 0.5f : 1.0f;

    // forward pair: value = F[i+f?1] - F[i+f?0]
    const int fx0 = (x == NN - 1) ? -SXX : 0;  const int fx1 = fx0 + SXX;
    const int fy0 = (y == NN - 1) ? -SYY : 0;  const int fy1 = fy0 + SYY;
    const int fz0 = (z == NN - 1) ? -1   : 0;  const int fz1 = fz0 + 1;

    // backward pair: value = F[i+b?1] - F[i+b?0]
    const int bx1 = (x == 0) ? SXX : 0;  const int bx0 = bx1 - SXX;
    const int by1 = (y == 0) ? SYY : 0;  const int by0 = by1 - SYY;
    const int bz1 = (z == 0) ? 1   : 0;  const int bz0 = bz1 - 1;

    // ---- central gradients of C ----
    const float cXC = (C[i + dxp] - C[i + dxm]) * wx;
    const float cYC = (C[i + dyp] - C[i + dym]) * wy;
    const float cZC = (C[i + dzp] - C[i + dzm]) * wz;

    // ---- divergence-of-D rows (central grads of D components) ----
    const float gx = (Dxx[i + dxp] - Dxx[i + dxm]) * wx
                   + (Dxy[i + dyp] - Dxy[i + dym]) * wy
                   + (Dxz[i + dzp] - Dxz[i + dzm]) * wz;
    const float gy = (Dxy[i + dxp] - Dxy[i + dxm]) * wx
                   + (Dyy[i + dyp] - Dyy[i + dym]) * wy
                   + (Dyz[i + dzp] - Dyz[i + dzm]) * wz;
    const float gz = (Dxz[i + dxp] - Dxz[i + dxm]) * wx
                   + (Dyz[i + dyp] - Dyz[i + dym]) * wy
                   + (Dzz[i + dzp] - Dzz[i + dzm]) * wz;

    // ---- same-axis second derivatives bwd(fwd(C)) ----
    const float sxx = (x == NN - 1) ? 0.0f
                    : (C[i + bx1 + SXX] - 2.0f * C[i + bx1] + C[i + bx1 - SXX]);
    const float syy = (y == NN - 1) ? 0.0f
                    : (C[i + by1 + SYY] - 2.0f * C[i + by1] + C[i + by1 - SYY]);
    const float szz = (z == NN - 1) ? 0.0f
                    : (C[i + bz1 + 1]   - 2.0f * C[i + bz1] + C[i + bz1 - 1]);

    // ---- mixed second derivatives dAb(dBf(C)) ----
    #define MIX(bA1, bA0, fB1, fB0) \
        ((C[i + (bA1) + (fB1)] - C[i + (bA1) + (fB0)]) - \
         (C[i + (bA0) + (fB1)] - C[i + (bA0) + (fB0)]))

    const float mXY = MIX(bx1, bx0, fy1, fy0);  // dXb(Cy_f)
    const float mYX = MIX(by1, by0, fx1, fx0);  // dYb(Cx_f)
    const float mYZ = MIX(by1, by0, fz1, fz0);  // dYb(Cz_f)
    const float mZY = MIX(bz1, bz0, fy1, fy0);  // dZb(Cy_f)
    const float mZX = MIX(bz1, bz0, fx1, fx0);  // dZb(Cx_f)
    const float mXZ = MIX(bx1, bx0, fz1, fz0);  // dXb(Cz_f)
    #undef MIX

    const float diff = gx * cXC + gy * cYC + gz * cZC
                     + Dxx[i] * sxx + Dyy[i] * syy + Dzz[i] * szz
                     + Dxy[i] * (mXY + mYX)
                     + Dyz[i] * (mYZ + mZY)
                     + Dxz[i] * (mZX + mXZ);

    // ---- upwind advection ----
    const float vx = Vx[i], vy = Vy[i], vz = Vz[i];

    const float bXC = C[i + bx1] - C[i + bx0];
    const float fXC = C[i + fx1] - C[i + fx0];
    const float bYC = C[i + by1] - C[i + by0];
    const float fYC = C[i + fy1] - C[i + fy0];
    const float bZC = C[i + bz1] - C[i + bz0];
    const float fZC = C[i + fz1] - C[i + fz0];

    const float Cux = (vx > 0.0f) ? bXC : fXC;
    const float Cuy = (vy > 0.0f) ? bYC : fYC;
    const float Cuz = (vz > 0.0f) ? bZC : fZC;

    const float divV = (Vx[i + dxp] - Vx[i + dxm]) * wx
                     + (Vy[i + dyp] - Vy[i + dym]) * wy
                     + (Vz[i + dzp] - Vz[i + dzm]) * wz;

    const float adv = -(vx * Cux + vy * Cuy + vz * Cuz) - C[i] * divV;

    out[i] = diff + adv;
}

extern "C" void kernel_launch(void* const* d_in, const int* in_sizes, int n_in,
                              void* d_out, int out_size)
{
    const float* C   = (const float*)d_in[0];
    const float* Vx  = (const float*)d_in[1];
    const float* Vy  = (const float*)d_in[2];
    const float* Vz  = (const float*)d_in[3];
    const float* Dxx = (const float*)d_in[4];
    const float* Dxy = (const float*)d_in[5];
    const float* Dxz = (const float*)d_in[6];
    const float* Dyy = (const float*)d_in[7];
    const float* Dyz = (const float*)d_in[8];
    const float* Dzz = (const float*)d_in[9];
    float* out = (float*)d_out;

    dim3 grid(NN, NN, 2);   // (y, x, batch)
    dim3 block(NN);         // one full z-row per block, coalesced
    piano_energy_kernel<<<grid, block>>>(C, Vx, Vy, Vz,
                                         Dxx, Dxy, Dxz, Dyy, Dyz, Dzz, out);
}

// round 4
// speedup vs baseline: 1.1158x; 1.1158x over previous
#include <cuda_runtime.h>

// PIANO_EnergyV on (2,160,160,160) fp32, h=1.
// Round 2: z-vectorized interior kernel (float4 / 4 voxels per thread) +
// scalar boundary kernel for the x/y frame. See derivative semantics notes.

#define NN 160
#define SX (NN*NN)
#define SY (NN)

__device__ __forceinline__ float4 ldg4(const float* __restrict__ p) {
    return *reinterpret_cast<const float4*>(p);
}

// Unified row indexing: r[k] holds value at z = z0 - 1 + k.
#define LOAD_MID4(dst, P, B) do { \
    float4 _q = ldg4((P) + (B) + z0); \
    dst[1] = _q.x; dst[2] = _q.y; dst[3] = _q.z; dst[4] = _q.w; } while (0)
#define LOAD_LO5(dst, P, B) do { \
    LOAD_MID4(dst, P, B); \
    dst[0] = lo_ok ? (P)[(B) + z0 - 1] : dst[1]; } while (0)
#define LOAD_HI5(dst, P, B) do { \
    LOAD_MID4(dst, P, B); \
    dst[5] = hi_ok ? (P)[(B) + z0 + 4] : dst[4]; } while (0)
#define LOAD_FULL6(dst, P, B) do { \
    LOAD_MID4(dst, P, B); \
    dst[0] = lo_ok ? (P)[(B) + z0 - 1] : dst[1]; \
    dst[5] = hi_ok ? (P)[(B) + z0 + 4] : dst[4]; } while (0)

// ---------------------------------------------------------------------------
// Interior kernel: x in [1,158], y in [1,158], all z. 4 z-voxels per thread.
// ---------------------------------------------------------------------------
__global__ __launch_bounds__(160)
void piano_interior(
    const float* __restrict__ C_,
    const float* __restrict__ Vx_,
    const float* __restrict__ Vy_,
    const float* __restrict__ Vz_,
    const float* __restrict__ Dxx_,
    const float* __restrict__ Dxy_,
    const float* __restrict__ Dxz_,
    const float* __restrict__ Dyy_,
    const float* __restrict__ Dyz_,
    const float* __restrict__ Dzz_,
    float* __restrict__ out)
{
    const int tid = threadIdx.x;
    const int t  = tid % 40;           // z chunk: voxels z0..z0+3
    const int ys = tid / 40;           // y sub-row within block
    const int y  = 1 + 4 * blockIdx.x + ys;
    if (y > NN - 2) return;
    const int x  = 1 + blockIdx.y;
    const int b  = blockIdx.z;
    const int z0 = 4 * t;
    const int base = ((b * NN + x) * NN + y) * NN;
    const bool lo_ok = (t > 0);
    const bool hi_ok = (t < 39);

    // ---- C rows (live throughout) ----
    float c00[6], cxm[6], cxp[6], cym[6], cyp[6], cq1[6], cq2[6];
    LOAD_FULL6(c00, C_, base);
    LOAD_HI5 (cxm, C_, base - SX);       // (x-1, y): needs z0..z0+4
    LOAD_LO5 (cxp, C_, base + SX);       // (x+1, y): needs z0-1..z0+3
    LOAD_HI5 (cym, C_, base - SY);       // (x, y-1)
    LOAD_LO5 (cyp, C_, base + SY);       // (x, y+1)
    LOAD_MID4(cq1, C_, base - SX + SY);  // (x-1, y+1)
    LOAD_MID4(cq2, C_, base + SX - SY);  // (x+1, y-1)

    float res[4], cXC[4], cYC[4], cZC[4];
    #pragma unroll
    for (int e = 0; e < 4; e++) {
        const int k = e + 1;
        const bool zlo = (e == 0) && (t == 0);
        const bool zhi = (e == 3) && (t == 39);
        cXC[e] = (cxp[k] - cxm[k]) * 0.5f;
        cYC[e] = (cyp[k] - cym[k]) * 0.5f;
        cZC[e] = zlo ? (c00[k+1] - c00[k])
               : zhi ? (c00[k]   - c00[k-1])
                     : (c00[k+1] - c00[k-1]) * 0.5f;
        res[e] = 0.0f;
    }

    { // Dxx: dXc(Dxx)*Cx_c + Dxx * dXb(Cx_f)
        float dc[6], dm[6], dp[6];
        LOAD_MID4(dc, Dxx_, base);
        LOAD_MID4(dm, Dxx_, base - SX);
        LOAD_MID4(dp, Dxx_, base + SX);
        #pragma unroll
        for (int e = 0; e < 4; e++) { const int k = e + 1;
            float sxx = cxp[k] - 2.0f * c00[k] + cxm[k];
            res[e] += (dp[k] - dm[k]) * 0.5f * cXC[e] + dc[k] * sxx;
        }
    }
    { // Dyy
        float dc[6], dm[6], dp[6];
        LOAD_MID4(dc, Dyy_, base);
        LOAD_MID4(dm, Dyy_, base - SY);
        LOAD_MID4(dp, Dyy_, base + SY);
        #pragma unroll
        for (int e = 0; e < 4; e++) { const int k = e + 1;
            float syy = cyp[k] - 2.0f * c00[k] + cym[k];
            res[e] += (dp[k] - dm[k]) * 0.5f * cYC[e] + dc[k] * syy;
        }
    }
    { // Dzz: dZc(Dzz)*Cz_c + Dzz * dZb(Cz_f)
        float dc[6];
        LOAD_FULL6(dc, Dzz_, base);
        #pragma unroll
        for (int e = 0; e < 4; e++) { const int k = e + 1;
            const bool zlo = (e == 0) && (t == 0);
            const bool zhi = (e == 3) && (t == 39);
            float cz  = zlo ? (dc[k+1] - dc[k])
                      : zhi ? (dc[k]   - dc[k-1])
                            : (dc[k+1] - dc[k-1]) * 0.5f;
            float szz = zhi ? 0.0f
                      : zlo ? (c00[k+2] - 2.0f * c00[k+1] + c00[k])
                            : (c00[k+1] - 2.0f * c00[k]   + c00[k-1]);
            res[e] += cz * cZC[e] + dc[k] * szz;
        }
    }
    { // Dxy: dXc(Dxy)*Cy_c + dYc(Dxy)*Cx_c + Dxy*(dXb(Cy_f)+dYb(Cx_f))
        float dc[6], dxm2[6], dxp2[6], dym2[6], dyp2[6];
        LOAD_MID4(dc,   Dxy_, base);
        LOAD_MID4(dxm2, Dxy_, base - SX);
        LOAD_MID4(dxp2, Dxy_, base + SX);
        LOAD_MID4(dym2, Dxy_, base - SY);
        LOAD_MID4(dyp2, Dxy_, base + SY);
        #pragma unroll
        for (int e = 0; e < 4; e++) { const int k = e + 1;
            float mXY = (cyp[k] - c00[k]) - (cq1[k] - cxm[k]);
            float mYX = (cxp[k] - c00[k]) - (cq2[k] - cym[k]);
            res[e] += (dxp2[k] - dxm2[k]) * 0.5f * cYC[e]
                    + (dyp2[k] - dym2[k]) * 0.5f * cXC[e]
                    + dc[k] * (mXY + mYX);
        }
    }
    { // Dxz: dZc(Dxz)*Cx_c + dXc(Dxz)*Cz_c + Dxz*(dZb(Cx_f)+dXb(Cz_f))
        float dc[6], dm[6], dp[6];
        LOAD_FULL6(dc, Dxz_, base);
        LOAD_MID4(dm, Dxz_, base - SX);
        LOAD_MID4(dp, Dxz_, base + SX);
        #pragma unroll
        for (int e = 0; e < 4; e++) { const int k = e + 1;
            const bool zlo = (e == 0) && (t == 0);
            const bool zhi = (e == 3) && (t == 39);
            float cz = zlo ? (dc[k+1] - dc[k])
                     : zhi ? (dc[k]   - dc[k-1])
                           : (dc[k+1] - dc[k-1]) * 0.5f;
            // mXZ = dXb(Cz_f): Cz_f(row) = zhi ? row[k]-row[k-1] : row[k+1]-row[k]
            float czf0 = zhi ? (c00[k] - c00[k-1]) : (c00[k+1] - c00[k]);
            float czfm = zhi ? (cxm[k] - cxm[k-1]) : (cxm[k+1] - cxm[k]);
            float mXZ = czf0 - czfm;
            // mZX = dZb(Cx_f): Cx_f(j) = cxp[j]-c00[j]
            float mZX = zlo ? ((cxp[k+1] - c00[k+1]) - (cxp[k]   - c00[k]))
                            : ((cxp[k]   - c00[k])   - (cxp[k-1] - c00[k-1]));
            res[e] += cz * cXC[e] + (dp[k] - dm[k]) * 0.5f * cZC[e]
                    + dc[k] * (mXZ + mZX);
        }
    }
    { // Dyz: dZc(Dyz)*Cy_c + dYc(Dyz)*Cz_c + Dyz*(dYb(Cz_f)+dZb(Cy_f))
        float dc[6], dm[6], dp[6];
        LOAD_FULL6(dc, Dyz_, base);
        LOAD_MID4(dm, Dyz_, base - SY);
        LOAD_MID4(dp, Dyz_, base + SY);
        #pragma unroll
        for (int e = 0; e < 4; e++) { const int k = e + 1;
            const bool zlo = (e == 0) && (t == 0);
            const bool zhi = (e == 3) && (t == 39);
            float cz = zlo ? (dc[k+1] - dc[k])
                     : zhi ? (dc[k]   - dc[k-1])
                           : (dc[k+1] - dc[k-1]) * 0.5f;
            float czf0 = zhi ? (c00[k] - c00[k-1]) : (c00[k+1] - c00[k]);
            float czfm = zhi ? (cym[k] - cym[k-1]) : (cym[k+1] - cym[k]);
            float mYZ = czf0 - czfm;
            float mZY = zlo ? ((cyp[k+1] - c00[k+1]) - (cyp[k]   - c00[k]))
                            : ((cyp[k]   - c00[k])   - (cyp[k-1] - c00[k-1]));
            res[e] += cz * cYC[e] + (dp[k] - dm[k]) * 0.5f * cZC[e]
                    + dc[k] * (mYZ + mZY);
        }
    }
    { // Advection: x
        float vc[6], vm[6], vp[6];
        LOAD_MID4(vc, Vx_, base);
        LOAD_MID4(vm, Vx_, base - SX);
        LOAD_MID4(vp, Vx_, base + SX);
        #pragma unroll
        for (int e = 0; e < 4; e++) { const int k = e + 1;
            float v = vc[k];
            float cb = c00[k] - cxm[k];
            float cf = cxp[k] - c00[k];
            float cu = (v > 0.0f) ? cb : cf;
            res[e] += -v * cu - c00[k] * ((vp[k] - vm[k]) * 0.5f);
        }
    }
    { // Advection: y
        float vc[6], vm[6], vp[6];
        LOAD_MID4(vc, Vy_, base);
        LOAD_MID4(vm, Vy_, base - SY);
        LOAD_MID4(vp, Vy_, base + SY);
        #pragma unroll
        for (int e = 0; e < 4; e++) { const int k = e + 1;
            float v = vc[k];
            float cb = c00[k] - cym[k];
            float cf = cyp[k] - c00[k];
            float cu = (v > 0.0f) ? cb : cf;
            res[e] += -v * cu - c00[k] * ((vp[k] - vm[k]) * 0.5f);
        }
    }
    { // Advection: z
        float vc[6];
        LOAD_FULL6(vc, Vz_, base);
        #pragma unroll
        for (int e = 0; e < 4; e++) { const int k = e + 1;
            const bool zlo = (e == 0) && (t == 0);
            const bool zhi = (e == 3) && (t == 39);
            float v  = vc[k];
            float cb = zlo ? (c00[k+1] - c00[k]) : (c00[k] - c00[k-1]);
            float cf = zhi ? (c00[k] - c00[k-1]) : (c00[k+1] - c00[k]);
            float cu = (v > 0.0f) ? cb : cf;
            float cz = zlo ? (vc[k+1] - vc[k])
                     : zhi ? (vc[k]   - vc[k-1])
                           : (vc[k+1] - vc[k-1]) * 0.5f;
            res[e] += -v * cu - c00[k] * cz;
        }
    }

    float4 o;
    o.x = res[0]; o.y = res[1]; o.z = res[2]; o.w = res[3];
    *reinterpret_cast<float4*>(out + base + z0) = o;
}

// ---------------------------------------------------------------------------
// Boundary kernel: rows with x in {0,159} (all y), or y in {0,159} (x 1..158).
// Round-1 scalar code (proven), one thread per voxel, one row per block.
// ---------------------------------------------------------------------------
__global__ __launch_bounds__(NN)
void piano_boundary(
    const float* __restrict__ C,
    const float* __restrict__ Vx,
    const float* __restrict__ Vy,
    const float* __restrict__ Vz,
    const float* __restrict__ Dxx,
    const float* __restrict__ Dxy,
    const float* __restrict__ Dxz,
    const float* __restrict__ Dyy,
    const float* __restrict__ Dyz,
    const float* __restrict__ Dzz,
    float* __restrict__ out)
{
    const int idx = blockIdx.x;
    int x, y;
    if (idx < 2 * NN) {                 // x-boundary rows
        x = (idx < NN) ? 0 : NN - 1;
        y = idx % NN;
    } else {                            // y-boundary rows, x in [1, 158]
        int r = idx - 2 * NN;
        x = 1 + (r >> 1);
        y = (r & 1) ? NN - 1 : 0;
    }
    const int b = blockIdx.y;
    const int z = threadIdx.x;
    const int i = ((b * NN + x) * NN + y) * NN + z;

    const int dxm = (x > 0)      ? -SX : 0;
    const int dxp = (x < NN - 1) ?  SX : 0;
    const float wx = (x > 0 && x < NN - 1) ? 0.5f : 1.0f;
    const int dym = (y > 0)      ? -SY : 0;
    const int dyp = (y < NN - 1) ?  SY : 0;
    const float wy = (y > 0 && y < NN - 1) ? 0.5f : 1.0f;
    const int dzm = (z > 0)      ? -1 : 0;
    const int dzp = (z < NN - 1) ?  1 : 0;
    const float wz = (z > 0 && z < NN - 1) ? 0.5f : 1.0f;

    const int fx0 = (x == NN - 1) ? -SX : 0;  const int fx1 = fx0 + SX;
    const int fy0 = (y == NN - 1) ? -SY : 0;  const int fy1 = fy0 + SY;
    const int fz0 = (z == NN - 1) ? -1  : 0;  const int fz1 = fz0 + 1;

    const int bx1 = (x == 0) ? SX : 0;  const int bx0 = bx1 - SX;
    const int by1 = (y == 0) ? SY : 0;  const int by0 = by1 - SY;
    const int bz1 = (z == 0) ? 1  : 0;  const int bz0 = bz1 - 1;

    const float cXC = (C[i + dxp] - C[i + dxm]) * wx;
    const float cYC = (C[i + dyp] - C[i + dym]) * wy;
    const float cZC = (C[i + dzp] - C[i + dzm]) * wz;

    const float gx = (Dxx[i + dxp] - Dxx[i + dxm]) * wx
                   + (Dxy[i + dyp] - Dxy[i + dym]) * wy
                   + (Dxz[i + dzp] - Dxz[i + dzm]) * wz;
    const float gy = (Dxy[i + dxp] - Dxy[i + dxm]) * wx
                   + (Dyy[i + dyp] - Dyy[i + dym]) * wy
                   + (Dyz[i + dzp] - Dyz[i + dzm]) * wz;
    const float gz = (Dxz[i + dxp] - Dxz[i + dxm]) * wx
                   + (Dyz[i + dyp] - Dyz[i + dym]) * wy
                   + (Dzz[i + dzp] - Dzz[i + dzm]) * wz;

    const float sxx = (x == NN - 1) ? 0.0f
                    : (C[i + bx1 + SX] - 2.0f * C[i + bx1] + C[i + bx1 - SX]);
    const float syy = (y == NN - 1) ? 0.0f
                    : (C[i + by1 + SY] - 2.0f * C[i + by1] + C[i + by1 - SY]);
    const float szz = (z == NN - 1) ? 0.0f
                    : (C[i + bz1 + 1]  - 2.0f * C[i + bz1] + C[i + bz1 - 1]);

    #define MIX(bA1, bA0, fB1, fB0) \
        ((C[i + (bA1) + (fB1)] - C[i + (bA1) + (fB0)]) - \
         (C[i + (bA0) + (fB1)] - C[i + (bA0) + (fB0)]))
    const float mXY = MIX(bx1, bx0, fy1, fy0);
    const float mYX = MIX(by1, by0, fx1, fx0);
    const float mYZ = MIX(by1, by0, fz1, fz0);
    const float mZY = MIX(bz1, bz0, fy1, fy0);
    const float mZX = MIX(bz1, bz0, fx1, fx0);
    const float mXZ = MIX(bx1, bx0, fz1, fz0);
    #undef MIX

    const float diff = gx * cXC + gy * cYC + gz * cZC
                     + Dxx[i] * sxx + Dyy[i] * syy + Dzz[i] * szz
                     + Dxy[i] * (mXY + mYX)
                     + Dyz[i] * (mYZ + mZY)
                     + Dxz[i] * (mZX + mXZ);

    const float vx = Vx[i], vy = Vy[i], vz = Vz[i];
    const float bXC = C[i + bx1] - C[i + bx0];
    const float fXC = C[i + fx1] - C[i + fx0];
    const float bYC = C[i + by1] - C[i + by0];
    const float fYC = C[i + fy1] - C[i + fy0];
    const float bZC = C[i + bz1] - C[i + bz0];
    const float fZC = C[i + fz1] - C[i + fz0];
    const float Cux = (vx > 0.0f) ? bXC : fXC;
    const float Cuy = (vy > 0.0f) ? bYC : fYC;
    const float Cuz = (vz > 0.0f) ? bZC : fZC;

    const float divV = (Vx[i + dxp] - Vx[i + dxm]) * wx
                     + (Vy[i + dyp] - Vy[i + dym]) * wy
                     + (Vz[i + dzp] - Vz[i + dzm]) * wz;

    const float adv = -(vx * Cux + vy * Cuy + vz * Cuz) - C[i] * divV;
    out[i] = diff + adv;
}

extern "C" void kernel_launch(void* const* d_in, const int* in_sizes, int n_in,
                              void* d_out, int out_size)
{
    const float* C   = (const float*)d_in[0];
    const float* Vx  = (const float*)d_in[1];
    const float* Vy  = (const float*)d_in[2];
    const float* Vz  = (const float*)d_in[3];
    const float* Dxx = (const float*)d_in[4];
    const float* Dxy = (const float*)d_in[5];
    const float* Dxz = (const float*)d_in[6];
    const float* Dyy = (const float*)d_in[7];
    const float* Dyz = (const float*)d_in[8];
    const float* Dzz = (const float*)d_in[9];
    float* out = (float*)d_out;

    // Interior: x in [1,158] (gridDim.y = 158), y in [1,158] via 40 y-quads.
    dim3 gi(40, NN - 2, 2);
    piano_interior<<<gi, 160>>>(C, Vx, Vy, Vz, Dxx, Dxy, Dxz, Dyy, Dyz, Dzz, out);

    // Boundary frame: 2*NN x-rows + 2*(NN-2) y-rows = 636 rows per batch.
    dim3 gb(2 * NN + 2 * (NN - 2), 2);
    piano_boundary<<<gb, NN>>>(C, Vx, Vy, Vz, Dxx, Dxy, Dxz, Dyy, Dyz, Dzz, out);
}

// round 7
// speedup vs baseline: 1.2396x; 1.1110x over previous
#include <cuda_runtime.h>

// PIANO_EnergyV on (2,160,160,160) fp32, h=1.
// Round 4: single merged kernel (interior z-vectorized path + boundary scalar
// path selected by blockIdx.x), grouped loads for MLP, register cap for
// occupancy.

#define NN 160
#define SX (NN*NN)
#define SY (NN)
#define NINT (40 * (NN - 2))          // 6320 interior blocks per batch
#define NBND (2 * NN + 2 * (NN - 2))  // 636 boundary row-blocks per batch

__device__ __forceinline__ float4 ldg4(const float* __restrict__ p) {
    return *reinterpret_cast<const float4*>(p);
}

// Row indexing: r[k] holds value at z = z0 - 1 + k.
#define LOAD_MID4(dst, P, B) do { \
    float4 _q = ldg4((P) + (B) + z0); \
    dst[1] = _q.x; dst[2] = _q.y; dst[3] = _q.z; dst[4] = _q.w; } while (0)
#define LOAD_LO5(dst, P, B) do { \
    LOAD_MID4(dst, P, B); \
    dst[0] = lo_ok ? (P)[(B) + z0 - 1] : dst[1]; } while (0)
#define LOAD_HI5(dst, P, B) do { \
    LOAD_MID4(dst, P, B); \
    dst[5] = hi_ok ? (P)[(B) + z0 + 4] : dst[4]; } while (0)
#define LOAD_FULL6(dst, P, B) do { \
    LOAD_MID4(dst, P, B); \
    dst[0] = lo_ok ? (P)[(B) + z0 - 1] : dst[1]; \
    dst[5] = hi_ok ? (P)[(B) + z0 + 4] : dst[4]; } while (0)

// ---------------------------------------------------------------------------
// Interior path: x in [1,158], y in [1,158], 4 z-voxels per thread.
// ---------------------------------------------------------------------------
__device__ __forceinline__ void interior_path(
    int bx, int b,
    const float* __restrict__ C_,
    const float* __restrict__ Vx_,
    const float* __restrict__ Vy_,
    const float* __restrict__ Vz_,
    const float* __restrict__ Dxx_,
    const float* __restrict__ Dxy_,
    const float* __restrict__ Dxz_,
    const float* __restrict__ Dyy_,
    const float* __restrict__ Dyz_,
    const float* __restrict__ Dzz_,
    float* __restrict__ out)
{
    const int tid = threadIdx.x;
    const int t  = tid % 40;            // z chunk
    const int ys = tid / 40;            // y sub-row
    const int yq = bx % 40;
    const int x  = 1 + bx / 40;
    const int y  = 1 + 4 * yq + ys;
    if (y > NN - 2) return;
    const int z0 = 4 * t;
    const int base = ((b * NN + x) * NN + y) * NN;
    const bool lo_ok = (t > 0);
    const bool hi_ok = (t < 39);

    // ---- C rows (live throughout) ----
    float c00[6], cxm[6], cxp[6], cym[6], cyp[6];
    LOAD_FULL6(c00, C_, base);
    LOAD_HI5 (cxm, C_, base - SX);
    LOAD_LO5 (cxp, C_, base + SX);
    LOAD_HI5 (cym, C_, base - SY);
    LOAD_LO5 (cyp, C_, base + SY);

    float res[4], cXC[4], cYC[4], cZC[4];
    #pragma unroll
    for (int e = 0; e < 4; e++) {
        const int k = e + 1;
        const bool zlo = (e == 0) && (t == 0);
        const bool zhi = (e == 3) && (t == 39);
        cXC[e] = (cxp[k] - cxm[k]) * 0.5f;
        cYC[e] = (cyp[k] - cym[k]) * 0.5f;
        cZC[e] = zlo ? (c00[k+1] - c00[k])
               : zhi ? (c00[k]   - c00[k-1])
                     : (c00[k+1] - c00[k-1]) * 0.5f;
        res[e] = 0.0f;
    }

    // ==== Group 1: diagonal D (Dxx, Dyy, Dzz) — 7 vec + 2 scalar LDG ====
    {
        float axc[6], axm[6], axp[6], ayc[6], aym[6], ayp[6], azc[6];
        LOAD_MID4(axc, Dxx_, base);
        LOAD_MID4(axm, Dxx_, base - SX);
        LOAD_MID4(axp, Dxx_, base + SX);
        LOAD_MID4(ayc, Dyy_, base);
        LOAD_MID4(aym, Dyy_, base - SY);
        LOAD_MID4(ayp, Dyy_, base + SY);
        LOAD_FULL6(azc, Dzz_, base);
        #pragma unroll
        for (int e = 0; e < 4; e++) { const int k = e + 1;
            const bool zlo = (e == 0) && (t == 0);
            const bool zhi = (e == 3) && (t == 39);
            float sxx = cxp[k] - 2.0f * c00[k] + cxm[k];
            float syy = cyp[k] - 2.0f * c00[k] + cym[k];
            float cz  = zlo ? (azc[k+1] - azc[k])
                      : zhi ? (azc[k]   - azc[k-1])
                            : (azc[k+1] - azc[k-1]) * 0.5f;
            float szz = zhi ? 0.0f
                      : zlo ? (c00[k+2] - 2.0f * c00[k+1] + c00[k])
                            : (c00[k+1] - 2.0f * c00[k]   + c00[k-1]);
            res[e] += (axp[k] - axm[k]) * 0.5f * cXC[e] + axc[k] * sxx
                    + (ayp[k] - aym[k]) * 0.5f * cYC[e] + ayc[k] * syy
                    + cz * cZC[e] + azc[k] * szz;
        }
    }
    // ==== Group 2: Dxy (+ xy corner C rows) — 7 vec LDG ====
    {
        float dc[6], dxm2[6], dxp2[6], dym2[6], dyp2[6], cq1[6], cq2[6];
        LOAD_MID4(dc,   Dxy_, base);
        LOAD_MID4(dxm2, Dxy_, base - SX);
        LOAD_MID4(dxp2, Dxy_, base + SX);
        LOAD_MID4(dym2, Dxy_, base - SY);
        LOAD_MID4(dyp2, Dxy_, base + SY);
        LOAD_MID4(cq1, C_, base - SX + SY);   // (x-1, y+1)
        LOAD_MID4(cq2, C_, base + SX - SY);   // (x+1, y-1)
        #pragma unroll
        for (int e = 0; e < 4; e++) { const int k = e + 1;
            float mXY = (cyp[k] - c00[k]) - (cq1[k] - cxm[k]);
            float mYX = (cxp[k] - c00[k]) - (cq2[k] - cym[k]);
            res[e] += (dxp2[k] - dxm2[k]) * 0.5f * cYC[e]
                    + (dyp2[k] - dym2[k]) * 0.5f * cXC[e]
                    + dc[k] * (mXY + mYX);
        }
    }
    // ==== Group 3: Dxz + Dyz — 6 vec + 4 scalar LDG ====
    {
        float ec[6], em[6], ep[6], fc[6], fm[6], fp[6];
        LOAD_FULL6(ec, Dxz_, base);
        LOAD_MID4 (em, Dxz_, base - SX);
        LOAD_MID4 (ep, Dxz_, base + SX);
        LOAD_FULL6(fc, Dyz_, base);
        LOAD_MID4 (fm, Dyz_, base - SY);
        LOAD_MID4 (fp, Dyz_, base + SY);
        #pragma unroll
        for (int e = 0; e < 4; e++) { const int k = e + 1;
            const bool zlo = (e == 0) && (t == 0);
            const bool zhi = (e == 3) && (t == 39);
            // --- Dxz ---
            float czE = zlo ? (ec[k+1] - ec[k])
                      : zhi ? (ec[k]   - ec[k-1])
                            : (ec[k+1] - ec[k-1]) * 0.5f;
            float czf0 = zhi ? (c00[k] - c00[k-1]) : (c00[k+1] - c00[k]);
            float czfx = zhi ? (cxm[k] - cxm[k-1]) : (cxm[k+1] - cxm[k]);
            float mXZ = czf0 - czfx;
            float mZX = zlo ? ((cxp[k+1] - c00[k+1]) - (cxp[k]   - c00[k]))
                            : ((cxp[k]   - c00[k])   - (cxp[k-1] - c00[k-1]));
            res[e] += czE * cXC[e] + (ep[k] - em[k]) * 0.5f * cZC[e]
                    + ec[k] * (mXZ + mZX);
            // --- Dyz ---
            float czF = zlo ? (fc[k+1] - fc[k])
                      : zhi ? (fc[k]   - fc[k-1])
                            : (fc[k+1] - fc[k-1]) * 0.5f;
            float czfy = zhi ? (cym[k] - cym[k-1]) : (cym[k+1] - cym[k]);
            float mYZ = czf0 - czfy;
            float mZY = zlo ? ((cyp[k+1] - c00[k+1]) - (cyp[k]   - c00[k]))
                            : ((cyp[k]   - c00[k])   - (cyp[k-1] - c00[k-1]));
            res[e] += czF * cYC[e] + (fp[k] - fm[k]) * 0.5f * cZC[e]
                    + fc[k] * (mYZ + mZY);
        }
    }
    // ==== Group 4: advection (Vx, Vy, Vz) — 7 vec + 2 scalar LDG ====
    {
        float vxc[6], vxm[6], vxp[6], vyc[6], vym[6], vyp[6], vzc[6];
        LOAD_MID4(vxc, Vx_, base);
        LOAD_MID4(vxm, Vx_, base - SX);
        LOAD_MID4(vxp, Vx_, base + SX);
        LOAD_MID4(vyc, Vy_, base);
        LOAD_MID4(vym, Vy_, base - SY);
        LOAD_MID4(vyp, Vy_, base + SY);
        LOAD_FULL6(vzc, Vz_, base);
        #pragma unroll
        for (int e = 0; e < 4; e++) { const int k = e + 1;
            const bool zlo = (e == 0) && (t == 0);
            const bool zhi = (e == 3) && (t == 39);
            float vx = vxc[k], vy = vyc[k], vz = vzc[k];
            float cbx = c00[k] - cxm[k];
            float cfx = cxp[k] - c00[k];
            float cby = c00[k] - cym[k];
            float cfy = cyp[k] - c00[k];
            float cbz = zlo ? (c00[k+1] - c00[k]) : (c00[k] - c00[k-1]);
            float cfz = zhi ? (c00[k] - c00[k-1]) : (c00[k+1] - c00[k]);
            float cux = (vx > 0.0f) ? cbx : cfx;
            float cuy = (vy > 0.0f) ? cby : cfy;
            float cuz = (vz > 0.0f) ? cbz : cfz;
            float dvz = zlo ? (vzc[k+1] - vzc[k])
                      : zhi ? (vzc[k]   - vzc[k-1])
                            : (vzc[k+1] - vzc[k-1]) * 0.5f;
            float divV = (vxp[k] - vxm[k]) * 0.5f
                       + (vyp[k] - vym[k]) * 0.5f
                       + dvz;
            res[e] += -(vx * cux + vy * cuy + vz * cuz) - c00[k] * divV;
        }
    }

    float4 o;
    o.x = res[0]; o.y = res[1]; o.z = res[2]; o.w = res[3];
    *reinterpret_cast<float4*>(out + base + z0) = o;
}

// ---------------------------------------------------------------------------
// Boundary path: rows with x in {0,159} (all y) or y in {0,159} (x 1..158).
// Scalar, one thread per voxel, one row per block. (Round-1 proven code.)
// ---------------------------------------------------------------------------
__device__ __forceinline__ void boundary_path(
    int idx, int b,
    const float* __restrict__ C,
    const float* __restrict__ Vx,
    const float* __restrict__ Vy,
    const float* __restrict__ Vz,
    const float* __restrict__ Dxx,
    const float* __restrict__ Dxy,
    const float* __restrict__ Dxz,
    const float* __restrict__ Dyy,
    const float* __restrict__ Dyz,
    const float* __restrict__ Dzz,
    float* __restrict__ out)
{
    int x, y;
    if (idx < 2 * NN) {
        x = (idx < NN) ? 0 : NN - 1;
        y = idx % NN;
    } else {
        int r = idx - 2 * NN;
        x = 1 + (r >> 1);
        y = (r & 1) ? NN - 1 : 0;
    }
    const int z = threadIdx.x;
    const int i = ((b * NN + x) * NN + y) * NN + z;

    const int dxm = (x > 0)      ? -SX : 0;
    const int dxp = (x < NN - 1) ?  SX : 0;
    const float wx = (x > 0 && x < NN - 1) ? 0.5f : 1.0f;
    const int dym = (y > 0)      ? -SY : 0;
    const int dyp = (y < NN - 1) ?  SY : 0;
    const float wy = (y > 0 && y < NN - 1) ? 0.5f : 1.0f;
    const int dzm = (z > 0)      ? -1 : 0;
    const int dzp = (z < NN - 1) ?  1 : 0;
    const float wz = (z > 0 && z < NN - 1) ? 0.5f : 1.0f;

    const int fx0 = (x == NN - 1) ? -SX : 0;  const int fx1 = fx0 + SX;
    const int fy0 = (y == NN - 1) ? -SY : 0;  const int fy1 = fy0 + SY;
    const int fz0 = (z == NN - 1) ? -1  : 0;  const int fz1 = fz0 + 1;

    const int bx1 = (x == 0) ? SX : 0;  const int bx0 = bx1 - SX;
    const int by1 = (y == 0) ? SY : 0;  const int by0 = by1 - SY;
    const int bz1 = (z == 0) ? 1  : 0;  const int bz0 = bz1 - 1;

    const float cXC = (C[i + dxp] - C[i + dxm]) * wx;
    const float cYC = (C[i + dyp] - C[i + dym]) * wy;
    const float cZC = (C[i + dzp] - C[i + dzm]) * wz;

    const float gx = (Dxx[i + dxp] - Dxx[i + dxm]) * wx
                   + (Dxy[i + dyp] - Dxy[i + dym]) * wy
                   + (Dxz[i + dzp] - Dxz[i + dzm]) * wz;
    const float gy = (Dxy[i + dxp] - Dxy[i + dxm]) * wx
                   + (Dyy[i + dyp] - Dyy[i + dym]) * wy
                   + (Dyz[i + dzp] - Dyz[i + dzm]) * wz;
    const float gz = (Dxz[i + dxp] - Dxz[i + dxm]) * wx
                   + (Dyz[i + dyp] - Dyz[i + dym]) * wy
                   + (Dzz[i + dzp] - Dzz[i + dzm]) * wz;

    const float sxx = (x == NN - 1) ? 0.0f
                    : (C[i + bx1 + SX] - 2.0f * C[i + bx1] + C[i + bx1 - SX]);
    const float syy = (y == NN - 1) ? 0.0f
                    : (C[i + by1 + SY] - 2.0f * C[i + by1] + C[i + by1 - SY]);
    const float szz = (z == NN - 1) ? 0.0f
                    : (C[i + bz1 + 1]  - 2.0f * C[i + bz1] + C[i + bz1 - 1]);

    #define MIX(bA1, bA0, fB1, fB0) \
        ((C[i + (bA1) + (fB1)] - C[i + (bA1) + (fB0)]) - \
         (C[i + (bA0) + (fB1)] - C[i + (bA0) + (fB0)]))
    const float mXY = MIX(bx1, bx0, fy1, fy0);
    const float mYX = MIX(by1, by0, fx1, fx0);
    const float mYZ = MIX(by1, by0, fz1, fz0);
    const float mZY = MIX(bz1, bz0, fy1, fy0);
    const float mZX = MIX(bz1, bz0, fx1, fx0);
    const float mXZ = MIX(bx1, bx0, fz1, fz0);
    #undef MIX

    const float diff = gx * cXC + gy * cYC + gz * cZC
                     + Dxx[i] * sxx + Dyy[i] * syy + Dzz[i] * szz
                     + Dxy[i] * (mXY + mYX)
                     + Dyz[i] * (mYZ + mZY)
                     + Dxz[i] * (mZX + mXZ);

    const float vx = Vx[i], vy = Vy[i], vz = Vz[i];
    const float bXC = C[i + bx1] - C[i + bx0];
    const float fXC = C[i + fx1] - C[i + fx0];
    const float bYC = C[i + by1] - C[i + by0];
    const float fYC = C[i + fy1] - C[i + fy0];
    const float bZC = C[i + bz1] - C[i + bz0];
    const float fZC = C[i + fz1] - C[i + fz0];
    const float Cux = (vx > 0.0f) ? bXC : fXC;
    const float Cuy = (vy > 0.0f) ? bYC : fYC;
    const float Cuz = (vz > 0.0f) ? bZC : fZC;

    const float divV = (Vx[i + dxp] - Vx[i + dxm]) * wx
                     + (Vy[i + dyp] - Vy[i + dym]) * wy
                     + (Vz[i + dzp] - Vz[i + dzm]) * wz;

    const float adv = -(vx * Cux + vy * Cuy + vz * Cuz) - C[i] * divV;
    out[i] = diff + adv;
}

// ---------------------------------------------------------------------------
// Merged kernel: blockIdx.x < NINT -> interior; else boundary.
// ---------------------------------------------------------------------------
__global__ __launch_bounds__(160, 4)
void piano_all(
    const float* __restrict__ C,
    const float* __restrict__ Vx,
    const float* __restrict__ Vy,
    const float* __restrict__ Vz,
    const float* __restrict__ Dxx,
    const float* __restrict__ Dxy,
    const float* __restrict__ Dxz,
    const float* __restrict__ Dyy,
    const float* __restrict__ Dyz,
    const float* __restrict__ Dzz,
    float* __restrict__ out)
{
    const int bx = blockIdx.x;
    const int b  = blockIdx.y;
    if (bx < NINT) {
        interior_path(bx, b, C, Vx, Vy, Vz, Dxx, Dxy, Dxz, Dyy, Dyz, Dzz, out);
    } else {
        boundary_path(bx - NINT, b, C, Vx, Vy, Vz,
                      Dxx, Dxy, Dxz, Dyy, Dyz, Dzz, out);
    }
}

extern "C" void kernel_launch(void* const* d_in, const int* in_sizes, int n_in,
                              void* d_out, int out_size)
{
    const float* C   = (const float*)d_in[0];
    const float* Vx  = (const float*)d_in[1];
    const float* Vy  = (const float*)d_in[2];
    const float* Vz  = (const float*)d_in[3];
    const float* Dxx = (const float*)d_in[4];
    const float* Dxy = (const float*)d_in[5];
    const float* Dxz = (const float*)d_in[6];
    const float* Dyy = (const float*)d_in[7];
    const float* Dyz = (const float*)d_in[8];
    const float* Dzz = (const float*)d_in[9];
    float* out = (float*)d_out;

    dim3 grid(NINT + NBND, 2);
    piano_all<<<grid, 160>>>(C, Vx, Vy, Vz, Dxx, Dxy, Dxz, Dyy, Dyz, Dzz, out);
}